// round 1
// baseline (speedup 1.0000x reference)
#include <cuda_runtime.h>
#include <cuda_fp16.h>
#include <cstdint>
#include <cstddef>

// Problem constants
#define B_   16
#define H_   64
#define W_   64
#define C_   256
#define HP   66
#define WP   66
#define NPOS (B_*H_*W_)     // 65536
#define KDIM 2048           // 8 * C
#define NDIM 256

// GEMM tiling
#define BM 128
#define BN 128
#define BK 32
#define LDS_STRIDE 40       // halves per smem row (80B: 16B-aligned, conflict-free)

// Scratch (static device globals; no allocation)
__device__ __align__(16) __half g_pad[(size_t)B_ * HP * WP * C_];  // ~35.7 MB
__device__ __align__(16) __half Mt[(size_t)NDIM * KDIM];           // 1 MB  Mt[o][d*256+c]

// DIRECTIONS = [(0,-1),(1,-1),(1,0),(1,1),(0,1),(-1,1),(-1,0),(-1,-1)]  (dx,dy)
__device__ const int c_dx[8] = { 0, 1, 1, 1, 0,-1,-1,-1};
__device__ const int c_dy[8] = {-1,-1, 0, 1, 1, 1, 0,-1};

// ---------------------------------------------------------------------------
// Kernel 1: fp32 -> fp16 with zero halo. shifted_d[y][x] = g[y-dy][x-dx]
//           g_pad[b][yp][xp] = g[b][yp-1][xp-1], border = 0.
// ---------------------------------------------------------------------------
__global__ void pad_convert_kernel(const float* __restrict__ g)
{
    const int pix = blockIdx.x;            // 0 .. B*HP*WP-1
    const int c2  = threadIdx.x;           // 0..127 -> 2 channels
    const int xp  = pix % WP;
    const int tmp = pix / WP;
    const int yp  = tmp % HP;
    const int b   = tmp / HP;

    __half2 v = __half2half2(__float2half(0.0f));
    if (yp >= 1 && yp <= H_ && xp >= 1 && xp <= W_) {
        const float2 f = *(const float2*)&g[(((size_t)b * H_ + (yp - 1)) * W_ + (xp - 1)) * C_ + c2 * 2];
        v = __floats2half2_rn(f.x, f.y);
    }
    *(__half2*)&g_pad[((size_t)pix) * C_ + c2 * 2] = v;
}

// ---------------------------------------------------------------------------
// Kernel 2: fold weights.  Mt[o][d*256+c] = sum_e Wd[d][c][e] * Wc[o][d*256+e]
// Block = (d, c-tile64, e-tile64): 8*4*4 = 128 blocks, 256 threads, 4x4/thread
// ---------------------------------------------------------------------------
__global__ void fold_weights_kernel(const float* __restrict__ Wd,
                                    const float* __restrict__ Wc)
{
    const int bid = blockIdx.x;
    const int d  = bid >> 4;
    const int ct = (bid >> 2) & 3;
    const int et = bid & 3;

    __shared__ float WdS[64][33];
    __shared__ float WcS[64][33];

    const int t  = threadIdx.x;
    const int tx = t & 15;           // e micro-tile
    const int ty = t >> 4;           // c micro-tile

    float acc[4][4];
    #pragma unroll
    for (int i = 0; i < 4; i++)
        #pragma unroll
        for (int j = 0; j < 4; j++) acc[i][j] = 0.0f;

    const float* WdBase = Wd + (size_t)d * C_ * C_ + (size_t)(ct * 64) * C_;  // rows: c
    const float* WcBase = Wc + (size_t)(et * 64) * KDIM + d * C_;             // rows: o

    const int ci  = t >> 2;
    const int kk0 = (t & 3) * 8;

    for (int k0 = 0; k0 < C_; k0 += 32) {
        const float* srcA = WdBase + (size_t)ci * C_   + k0 + kk0;
        const float* srcB = WcBase + (size_t)ci * KDIM + k0 + kk0;
        #pragma unroll
        for (int u = 0; u < 8; u++) WdS[ci][kk0 + u] = srcA[u];
        #pragma unroll
        for (int u = 0; u < 8; u++) WcS[ci][kk0 + u] = srcB[u];
        __syncthreads();

        #pragma unroll
        for (int kk = 0; kk < 32; kk++) {
            float a[4], bb[4];
            #pragma unroll
            for (int i = 0; i < 4; i++) a[i]  = WdS[ty * 4 + i][kk];
            #pragma unroll
            for (int j = 0; j < 4; j++) bb[j] = WcS[tx * 4 + j][kk];
            #pragma unroll
            for (int i = 0; i < 4; i++)
                #pragma unroll
                for (int j = 0; j < 4; j++) acc[i][j] += a[i] * bb[j];
        }
        __syncthreads();
    }

    #pragma unroll
    for (int i = 0; i < 4; i++) {
        const int c = ct * 64 + ty * 4 + i;
        #pragma unroll
        for (int j = 0; j < 4; j++) {
            const int o = et * 64 + tx * 4 + j;
            Mt[(size_t)o * KDIM + d * C_ + c] = __float2half(acc[i][j]);
        }
    }
}

// ---------------------------------------------------------------------------
// Kernel 3: implicit-GEMM main kernel (mma.sync m16n8k16 f16->f32)
// out[pos][o] = bc[o] + sum_k A[pos][k] * Mt[o][k],
//   A[pos][d*256+c] = g_pad[b][y+1-dy_d][x+1-dx_d][c]
// ---------------------------------------------------------------------------
__device__ __forceinline__ void load_stage(int kt, int b, int y, int x, int lseg,
                                           const __half* __restrict__ mtrow,
                                           uint4& ra0, uint4& ra1,
                                           uint4& rb0, uint4& rb1)
{
    const int k0 = kt * BK;
    const int d  = k0 >> 8;
    const int cc = (k0 & 255) + lseg;
    const int yp = y + 1 - c_dy[d];
    const int xp = x + 1 - c_dx[d];
    const __half* pa = &g_pad[(((size_t)(b * HP + yp)) * WP + xp) * C_ + cc];
    ra0 = *(const uint4*)(pa);
    ra1 = *(const uint4*)(pa + 8);
    const __half* pb = mtrow + k0;
    rb0 = *(const uint4*)(pb);
    rb1 = *(const uint4*)(pb + 8);
}

__device__ __forceinline__ void store_stage(__half* __restrict__ As_,
                                            __half* __restrict__ Bs_,
                                            int lrow, int lseg,
                                            uint4 ra0, uint4 ra1,
                                            uint4 rb0, uint4 rb1)
{
    __half* pa = As_ + lrow * LDS_STRIDE + lseg;
    *(uint4*)(pa)     = ra0;
    *(uint4*)(pa + 8) = ra1;
    __half* pb = Bs_ + lrow * LDS_STRIDE + lseg;
    *(uint4*)(pb)     = rb0;
    *(uint4*)(pb + 8) = rb1;
}

__device__ __forceinline__ void compute_stage(const __half* __restrict__ As_,
                                              const __half* __restrict__ Bs_,
                                              int wm, int wn, int g, int tq,
                                              float acc[4][4][4])
{
    #pragma unroll
    for (int kk = 0; kk < 2; kk++) {
        uint32_t afr[4][4];
        uint32_t bfr[4][2];
        #pragma unroll
        for (int im = 0; im < 4; im++) {
            const __half* base = As_ + (wm + im * 16 + g) * LDS_STRIDE + kk * 16 + tq * 2;
            afr[im][0] = *(const uint32_t*)(base);
            afr[im][1] = *(const uint32_t*)(base + 8 * LDS_STRIDE);
            afr[im][2] = *(const uint32_t*)(base + 8);
            afr[im][3] = *(const uint32_t*)(base + 8 * LDS_STRIDE + 8);
        }
        #pragma unroll
        for (int jn = 0; jn < 4; jn++) {
            const __half* base = Bs_ + (wn + jn * 8 + g) * LDS_STRIDE + kk * 16 + tq * 2;
            bfr[jn][0] = *(const uint32_t*)(base);
            bfr[jn][1] = *(const uint32_t*)(base + 8);
        }
        #pragma unroll
        for (int im = 0; im < 4; im++)
            #pragma unroll
            for (int jn = 0; jn < 4; jn++)
                asm volatile(
                    "mma.sync.aligned.m16n8k16.row.col.f32.f16.f16.f32 "
                    "{%0,%1,%2,%3}, {%4,%5,%6,%7}, {%8,%9}, {%0,%1,%2,%3};\n"
                    : "+f"(acc[im][jn][0]), "+f"(acc[im][jn][1]),
                      "+f"(acc[im][jn][2]), "+f"(acc[im][jn][3])
                    : "r"(afr[im][0]), "r"(afr[im][1]),
                      "r"(afr[im][2]), "r"(afr[im][3]),
                      "r"(bfr[jn][0]), "r"(bfr[jn][1]));
    }
}

__global__ __launch_bounds__(256) void conv_gemm_kernel(const float* __restrict__ bias,
                                                        float* __restrict__ out)
{
    __shared__ __align__(16) __half As[2][BM * LDS_STRIDE];
    __shared__ __align__(16) __half Bs[2][BN * LDS_STRIDE];

    const int t    = threadIdx.x;
    const int m0   = (int)(blockIdx.x >> 1) * BM;   // 512 m-blocks
    const int n0   = (int)(blockIdx.x & 1) * BN;    // 2 n-blocks
    const int warp = t >> 5, lane = t & 31;
    const int wm   = (warp >> 2) * 64;              // 2 warps in M
    const int wn   = (warp & 3) * 32;               // 4 warps in N
    const int g    = lane >> 2, tq = lane & 3;

    const int lrow = t >> 1;                        // 0..127
    const int lseg = (t & 1) << 4;                  // 0 or 16 halves

    // position for this thread's A-load row
    const int m = m0 + lrow;
    const int x = m & 63;
    const int y = (m >> 6) & 63;
    const int b = m >> 12;

    const __half* mtrow = &Mt[(size_t)(n0 + lrow) * KDIM + lseg];

    float acc[4][4][4];
    #pragma unroll
    for (int i = 0; i < 4; i++)
        #pragma unroll
        for (int j = 0; j < 4; j++)
            #pragma unroll
            for (int r = 0; r < 4; r++) acc[i][j][r] = 0.0f;

    uint4 ra0, ra1, rb0, rb1;
    load_stage(0, b, y, x, lseg, mtrow, ra0, ra1, rb0, rb1);
    store_stage(&As[0][0], &Bs[0][0], lrow, lseg, ra0, ra1, rb0, rb1);
    __syncthreads();

    int buf = 0;
    const int NKT = KDIM / BK;   // 64
    for (int kt = 0; kt < NKT; kt++) {
        uint4 na0, na1, nb0, nb1;
        if (kt + 1 < NKT)
            load_stage(kt + 1, b, y, x, lseg, mtrow, na0, na1, nb0, nb1);

        compute_stage(&As[buf][0], &Bs[buf][0], wm, wn, g, tq, acc);

        if (kt + 1 < NKT) {
            store_stage(&As[buf ^ 1][0], &Bs[buf ^ 1][0], lrow, lseg, na0, na1, nb0, nb1);
            __syncthreads();
            buf ^= 1;
        }
    }

    // Epilogue: += bias, write fp32
    #pragma unroll
    for (int jn = 0; jn < 4; jn++) {
        const int n = n0 + wn + jn * 8 + tq * 2;
        const float2 bv = *(const float2*)&bias[n];
        #pragma unroll
        for (int im = 0; im < 4; im++) {
            const int mrow = m0 + wm + im * 16 + g;
            float2 v0, v1;
            v0.x = acc[im][jn][0] + bv.x;  v0.y = acc[im][jn][1] + bv.y;
            v1.x = acc[im][jn][2] + bv.x;  v1.y = acc[im][jn][3] + bv.y;
            *(float2*)&out[(size_t)mrow * NDIM + n]       = v0;
            *(float2*)&out[(size_t)(mrow + 8) * NDIM + n] = v1;
        }
    }
}

// ---------------------------------------------------------------------------
extern "C" void kernel_launch(void* const* d_in, const int* in_sizes, int n_in,
                              void* d_out, int out_size)
{
    const float* grid = (const float*)d_in[0];   // [16,64,64,256]
    const float* Wd   = (const float*)d_in[1];   // [8,256,256]
    const float* Wc   = (const float*)d_in[2];   // [256,2048]
    const float* bc   = (const float*)d_in[3];   // [256]
    float* out        = (float*)d_out;           // [16,64,64,256]

    pad_convert_kernel<<<B_ * HP * WP, 128>>>(grid);
    fold_weights_kernel<<<128, 256>>>(Wd, Wc);
    conv_gemm_kernel<<<(NPOS / BM) * (NDIM / BN), 256>>>(bc, out);
}

// round 3
// speedup vs baseline: 1.0714x; 1.0714x over previous
#include <cuda_runtime.h>
#include <cuda_fp16.h>
#include <cstdint>
#include <cstddef>

#define B_   16
#define H_   64
#define W_   64
#define C_   256
#define HP   66
#define WP   66
#define NPOS (B_*H_*W_)     // 65536
#define KDIM 2048
#define NDIM 256

#define BM 128
#define BN 256
#define BK 64               // halves per k-stage (128 B per row)
#define NKT (KDIM / BK)     // 32
#define NSTAGE 3

#define A_BYTES (BM * 128)            // 16 KB
#define B_BYTES (BN * 128)            // 32 KB
#define STAGE_BYTES (A_BYTES + B_BYTES)   // 48 KB
#define SM_TOTAL (NSTAGE * STAGE_BYTES)   // 144 KB

__device__ __align__(16) __half g_pad[(size_t)B_ * HP * WP * C_];  // ~35.7 MB
__device__ __align__(16) __half Mt[(size_t)NDIM * KDIM];           // 1 MB

// shift[d] = -dy[d]*WP - dx[d]
__device__ const int c_shift[8] = { 66, 65, -1, -67, -66, -65, 1, 67 };

// ---------------------------------------------------------------------------
__device__ __forceinline__ uint32_t smem_u32(const void* p) {
    uint32_t a;
    asm("{ .reg .u64 t; cvta.to.shared.u64 t, %1; cvt.u32.u64 %0, t; }" : "=r"(a) : "l"(p));
    return a;
}
__device__ __forceinline__ void cp_async16(uint32_t dst, const void* src) {
    asm volatile("cp.async.cg.shared.global [%0], [%1], 16;" :: "r"(dst), "l"(src));
}
__device__ __forceinline__ void cp_commit() {
    asm volatile("cp.async.commit_group;" ::: "memory");
}
template<int N> __device__ __forceinline__ void cp_wait() {
    asm volatile("cp.async.wait_group %0;" :: "n"(N) : "memory");
}
__device__ __forceinline__ void ldsm4(uint32_t& r0, uint32_t& r1, uint32_t& r2, uint32_t& r3,
                                      uint32_t addr) {
    asm volatile("ldmatrix.sync.aligned.m8n8.x4.shared.b16 {%0,%1,%2,%3}, [%4];"
                 : "=r"(r0), "=r"(r1), "=r"(r2), "=r"(r3) : "r"(addr));
}
__device__ __forceinline__ void mma16816(float* d, const uint32_t* a, const uint32_t* b) {
    asm volatile(
        "mma.sync.aligned.m16n8k16.row.col.f32.f16.f16.f32 "
        "{%0,%1,%2,%3}, {%4,%5,%6,%7}, {%8,%9}, {%0,%1,%2,%3};\n"
        : "+f"(d[0]), "+f"(d[1]), "+f"(d[2]), "+f"(d[3])
        : "r"(a[0]), "r"(a[1]), "r"(a[2]), "r"(a[3]), "r"(b[0]), "r"(b[1]));
}

// ---------------------------------------------------------------------------
// Kernel 1: pad + fp32->fp16 (zero halo)
// ---------------------------------------------------------------------------
__global__ __launch_bounds__(256) void pad_convert_kernel(const float* __restrict__ g)
{
    const int gid = blockIdx.x * 256 + threadIdx.x;
    const int pix = gid >> 6;
    const int c4  = (gid & 63) * 4;
    const int xp  = pix % WP;
    const int tmp = pix / WP;
    const int yp  = tmp % HP;
    const int b   = tmp / HP;

    uint2 v = make_uint2(0u, 0u);
    if (yp >= 1 && yp <= H_ && xp >= 1 && xp <= W_) {
        const float4 f = *(const float4*)&g[(((size_t)b * H_ + (yp - 1)) * W_ + (xp - 1)) * C_ + c4];
        __half2 lo = __floats2half2_rn(f.x, f.y);
        __half2 hi = __floats2half2_rn(f.z, f.w);
        v.x = *(uint32_t*)&lo;
        v.y = *(uint32_t*)&hi;
    }
    *(uint2*)&g_pad[(size_t)pix * C_ + c4] = v;
}

// ---------------------------------------------------------------------------
// Kernel 2: fold weights  Mt[o][d*256+c] = sum_e Wd[d][c][e] * Wc[o][d*256+e]
// ---------------------------------------------------------------------------
__global__ void fold_weights_kernel(const float* __restrict__ Wd,
                                    const float* __restrict__ Wc)
{
    const int bid = blockIdx.x;
    const int d  = bid >> 4;
    const int ct = (bid >> 2) & 3;
    const int et = bid & 3;

    __shared__ float WdS[64][33];
    __shared__ float WcS[64][33];

    const int t  = threadIdx.x;
    const int tx = t & 15;
    const int ty = t >> 4;

    float acc[4][4];
    #pragma unroll
    for (int i = 0; i < 4; i++)
        #pragma unroll
        for (int j = 0; j < 4; j++) acc[i][j] = 0.0f;

    const float* WdBase = Wd + (size_t)d * C_ * C_ + (size_t)(ct * 64) * C_;
    const float* WcBase = Wc + (size_t)(et * 64) * KDIM + d * C_;

    const int ci  = t >> 2;
    const int kk0 = (t & 3) * 8;

    for (int k0 = 0; k0 < C_; k0 += 32) {
        const float* srcA = WdBase + (size_t)ci * C_   + k0 + kk0;
        const float* srcB = WcBase + (size_t)ci * KDIM + k0 + kk0;
        #pragma unroll
        for (int u = 0; u < 8; u++) WdS[ci][kk0 + u] = srcA[u];
        #pragma unroll
        for (int u = 0; u < 8; u++) WcS[ci][kk0 + u] = srcB[u];
        __syncthreads();
        #pragma unroll
        for (int kk = 0; kk < 32; kk++) {
            float a[4], bb[4];
            #pragma unroll
            for (int i = 0; i < 4; i++) a[i]  = WdS[ty * 4 + i][kk];
            #pragma unroll
            for (int j = 0; j < 4; j++) bb[j] = WcS[tx * 4 + j][kk];
            #pragma unroll
            for (int i = 0; i < 4; i++)
                #pragma unroll
                for (int j = 0; j < 4; j++) acc[i][j] += a[i] * bb[j];
        }
        __syncthreads();
    }
    #pragma unroll
    for (int i = 0; i < 4; i++) {
        const int c = ct * 64 + ty * 4 + i;
        #pragma unroll
        for (int j = 0; j < 4; j++) {
            const int o = et * 64 + tx * 4 + j;
            Mt[(size_t)o * KDIM + d * C_ + c] = __float2half(acc[i][j]);
        }
    }
}

// ---------------------------------------------------------------------------
// Kernel 3: HMMA implicit-GEMM, cp.async 3-stage + ldmatrix.
// BM=128, BN=256 (full N), BK=64. 8 warps, each 64x64. 512 CTAs.
// ---------------------------------------------------------------------------
__global__ __launch_bounds__(256, 1) void conv_gemm_hmma(const float* __restrict__ bias,
                                                         float* __restrict__ out)
{
    extern __shared__ __align__(1024) char smem[];
    const uint32_t sbase = smem_u32(smem);

    const int t    = threadIdx.x;
    const int warp = t >> 5, lane = t & 31;
    const int m0   = blockIdx.x * BM;

    // ---- producer setup: A row t/2 (4 chunks), B row t (8 chunks) ----
    const int arow = t >> 1;
    {
        // nothing
    }
    const int m = m0 + arow;
    const int x = m & 63;
    const int y = (m >> 6) & 63;
    const int b = m >> 12;
    const __half* a_src_base = g_pad + (size_t)((b * HP + y + 1) * WP + (x + 1)) * C_;
    const __half* b_src_base = Mt + (size_t)t * KDIM;

    uint32_t a_dst[4], b_dst[8];
    #pragma unroll
    for (int j = 0; j < 4; j++) {
        const int cj = (t & 1) * 4 + j;
        a_dst[j] = (uint32_t)(arow * 128 + ((cj ^ (arow & 7)) << 4));
    }
    #pragma unroll
    for (int j = 0; j < 8; j++)
        b_dst[j] = (uint32_t)(A_BYTES + t * 128 + ((j ^ (t & 7)) << 4));

    // ---- consumer setup: warp tile 64x64 ----
    const int wm = (warp >> 2) * 64;          // 2 warps in M
    const int wn = (warp & 3) * 64;           // 4 warps in N
    const int swz   = lane & 7;
    const int a_hi  = lane >> 4;              // 0/1
    const int b_hi  = (lane >> 3) & 1;        // 0/1

    uint32_t a_row_off[4], b_row_off[4];
    #pragma unroll
    for (int im = 0; im < 4; im++)
        a_row_off[im] = (uint32_t)((wm + im * 16 + (lane & 15)) * 128);
    #pragma unroll
    for (int j2 = 0; j2 < 4; j2++)
        b_row_off[j2] = (uint32_t)(A_BYTES +
            (wn + j2 * 16 + ((lane >> 4) << 3) + (lane & 7)) * 128);

    float acc[4][8][4];
    #pragma unroll
    for (int i = 0; i < 4; i++)
        #pragma unroll
        for (int j = 0; j < 8; j++)
            #pragma unroll
            for (int r = 0; r < 4; r++) acc[i][j][r] = 0.0f;

    // ---- pipeline ----
    #define LOAD_STAGE(KT, S)                                                     \
    do {                                                                          \
        const int d_   = (KT) >> 2;                                               \
        const int coff = ((KT) & 3) * 64 + (t & 1) * 32;                          \
        const __half* asrc = a_src_base + c_shift[d_] * C_ + coff;                \
        const __half* bsrc = b_src_base + (KT) * 64;                              \
        const uint32_t sb  = sbase + (S) * STAGE_BYTES;                           \
        _Pragma("unroll")                                                         \
        for (int j = 0; j < 4; j++) cp_async16(sb + a_dst[j], asrc + j * 8);      \
        _Pragma("unroll")                                                         \
        for (int j = 0; j < 8; j++) cp_async16(sb + b_dst[j], bsrc + j * 8);      \
        cp_commit();                                                              \
    } while (0)

    LOAD_STAGE(0, 0);
    LOAD_STAGE(1, 1);

    for (int s = 0; s < NKT; s++) {
        if (s + 2 < NKT) cp_wait<1>(); else cp_wait<0>();
        __syncthreads();
        if (s + 2 < NKT) LOAD_STAGE(s + 2, (s + 2) % NSTAGE);

        const uint32_t sb = sbase + (s % NSTAGE) * STAGE_BYTES;
        #pragma unroll
        for (int kk = 0; kk < 4; kk++) {
            uint32_t afr[4][4];
            uint32_t bfr[8][2];
            #pragma unroll
            for (int im = 0; im < 4; im++)
                ldsm4(afr[im][0], afr[im][1], afr[im][2], afr[im][3],
                      sb + a_row_off[im] + (((kk * 2 + a_hi) ^ swz) << 4));
            #pragma unroll
            for (int j2 = 0; j2 < 4; j2++) {
                uint32_t r0, r1, r2, r3;
                ldsm4(r0, r1, r2, r3,
                      sb + b_row_off[j2] + (((kk * 2 + b_hi) ^ swz) << 4));
                bfr[j2 * 2 + 0][0] = r0; bfr[j2 * 2 + 0][1] = r1;
                bfr[j2 * 2 + 1][0] = r2; bfr[j2 * 2 + 1][1] = r3;
            }
            #pragma unroll
            for (int im = 0; im < 4; im++)
                #pragma unroll
                for (int jn = 0; jn < 8; jn++)
                    mma16816(acc[im][jn], afr[im], bfr[jn]);
        }
    }

    // ---- epilogue ----
    #pragma unroll
    for (int jn = 0; jn < 8; jn++) {
        const int n = wn + jn * 8 + (lane & 3) * 2;
        const float2 bv = *(const float2*)&bias[n];
        #pragma unroll
        for (int im = 0; im < 4; im++) {
            const int mrow = m0 + wm + im * 16 + (lane >> 2);
            float2 v0, v1;
            v0.x = acc[im][jn][0] + bv.x;  v0.y = acc[im][jn][1] + bv.y;
            v1.x = acc[im][jn][2] + bv.x;  v1.y = acc[im][jn][3] + bv.y;
            *(float2*)&out[(size_t)mrow * NDIM + n]       = v0;
            *(float2*)&out[(size_t)(mrow + 8) * NDIM + n] = v1;
        }
    }
}

// ---------------------------------------------------------------------------
extern "C" void kernel_launch(void* const* d_in, const int* in_sizes, int n_in,
                              void* d_out, int out_size)
{
    const float* grid = (const float*)d_in[0];
    const float* Wd   = (const float*)d_in[1];
    const float* Wc   = (const float*)d_in[2];
    const float* bc   = (const float*)d_in[3];
    float* out        = (float*)d_out;

    cudaFuncSetAttribute(conv_gemm_hmma, cudaFuncAttributeMaxDynamicSharedMemorySize, SM_TOTAL);

    pad_convert_kernel<<<(B_ * HP * WP * 64) / 256, 256>>>(grid);
    fold_weights_kernel<<<128, 256>>>(Wd, Wc);
    conv_gemm_hmma<<<NPOS / BM, 256, SM_TOTAL>>>(bc, out);
}

// round 4
// speedup vs baseline: 1.3110x; 1.2237x over previous
#include <cuda_runtime.h>
#include <cuda_fp16.h>
#include <cstdint>
#include <cstddef>

#define B_   16
#define H_   64
#define W_   64
#define C_   256
#define HP   66
#define WP   66
#define NPOS (B_*H_*W_)     // 65536
#define KDIM 2048
#define NDIM 256

#define BM 64
#define BN 128
#define BK 64               // halves per k-stage (128 B per row)
#define NKT (KDIM / BK)     // 32
#define NSTAGE 3

#define A_BYTES (BM * 128)                 // 8 KB
#define B_BYTES (BN * 128)                 // 16 KB
#define STAGE_BYTES (A_BYTES + B_BYTES)    // 24 KB
#define SM_TOTAL (NSTAGE * STAGE_BYTES)    // 72 KB -> 2+ CTAs/SM

__device__ __align__(16) __half g_pad[(size_t)B_ * HP * WP * C_];  // ~35.7 MB
__device__ __align__(16) __half Mt[(size_t)NDIM * KDIM];           // 1 MB

// shift[d] = -dy[d]*WP - dx[d]
__device__ const int c_shift[8] = { 66, 65, -1, -67, -66, -65, 1, 67 };

// ---------------------------------------------------------------------------
__device__ __forceinline__ uint32_t smem_u32(const void* p) {
    uint32_t a;
    asm("{ .reg .u64 t; cvta.to.shared.u64 t, %1; cvt.u32.u64 %0, t; }" : "=r"(a) : "l"(p));
    return a;
}
__device__ __forceinline__ void cp_async16(uint32_t dst, const void* src) {
    asm volatile("cp.async.cg.shared.global [%0], [%1], 16;" :: "r"(dst), "l"(src));
}
__device__ __forceinline__ void cp_commit() {
    asm volatile("cp.async.commit_group;" ::: "memory");
}
template<int N> __device__ __forceinline__ void cp_wait() {
    asm volatile("cp.async.wait_group %0;" :: "n"(N) : "memory");
}
__device__ __forceinline__ void ldsm4(uint32_t& r0, uint32_t& r1, uint32_t& r2, uint32_t& r3,
                                      uint32_t addr) {
    asm volatile("ldmatrix.sync.aligned.m8n8.x4.shared.b16 {%0,%1,%2,%3}, [%4];"
                 : "=r"(r0), "=r"(r1), "=r"(r2), "=r"(r3) : "r"(addr));
}
__device__ __forceinline__ void mma16816(float* d, const uint32_t* a, const uint32_t* b) {
    asm volatile(
        "mma.sync.aligned.m16n8k16.row.col.f32.f16.f16.f32 "
        "{%0,%1,%2,%3}, {%4,%5,%6,%7}, {%8,%9}, {%0,%1,%2,%3};\n"
        : "+f"(d[0]), "+f"(d[1]), "+f"(d[2]), "+f"(d[3])
        : "r"(a[0]), "r"(a[1]), "r"(a[2]), "r"(a[3]), "r"(b[0]), "r"(b[1]));
}

// ---------------------------------------------------------------------------
// Kernel 1: pad + fp32->fp16 (zero halo), 8 halves per thread
// ---------------------------------------------------------------------------
__global__ __launch_bounds__(256) void pad_convert_kernel(const float* __restrict__ g)
{
    const int gid = blockIdx.x * 256 + threadIdx.x;   // one per 8 channels
    const int pix = gid >> 5;
    const int c8  = (gid & 31) * 8;
    const int xp  = pix % WP;
    const int tmp = pix / WP;
    const int yp  = tmp % HP;
    const int b   = tmp / HP;

    uint4 v = make_uint4(0u, 0u, 0u, 0u);
    if (yp >= 1 && yp <= H_ && xp >= 1 && xp <= W_) {
        const float* src = &g[(((size_t)b * H_ + (yp - 1)) * W_ + (xp - 1)) * C_ + c8];
        const float4 f0 = *(const float4*)(src);
        const float4 f1 = *(const float4*)(src + 4);
        __half2 h0 = __floats2half2_rn(f0.x, f0.y);
        __half2 h1 = __floats2half2_rn(f0.z, f0.w);
        __half2 h2 = __floats2half2_rn(f1.x, f1.y);
        __half2 h3 = __floats2half2_rn(f1.z, f1.w);
        v.x = *(uint32_t*)&h0; v.y = *(uint32_t*)&h1;
        v.z = *(uint32_t*)&h2; v.w = *(uint32_t*)&h3;
    }
    *(uint4*)&g_pad[(size_t)pix * C_ + c8] = v;
}

// ---------------------------------------------------------------------------
// Kernel 2: fold weights  Mt[o][d*256+c] = sum_e Wd[d][c][e] * Wc[o][d*256+e]
// ---------------------------------------------------------------------------
__global__ void fold_weights_kernel(const float* __restrict__ Wd,
                                    const float* __restrict__ Wc)
{
    const int bid = blockIdx.x;
    const int d  = bid >> 4;
    const int ct = (bid >> 2) & 3;
    const int et = bid & 3;

    __shared__ float WdS[64][33];
    __shared__ float WcS[64][33];

    const int t  = threadIdx.x;
    const int tx = t & 15;
    const int ty = t >> 4;

    float acc[4][4];
    #pragma unroll
    for (int i = 0; i < 4; i++)
        #pragma unroll
        for (int j = 0; j < 4; j++) acc[i][j] = 0.0f;

    const float* WdBase = Wd + (size_t)d * C_ * C_ + (size_t)(ct * 64) * C_;
    const float* WcBase = Wc + (size_t)(et * 64) * KDIM + d * C_;

    const int ci  = t >> 2;
    const int kk0 = (t & 3) * 8;

    for (int k0 = 0; k0 < C_; k0 += 32) {
        const float* srcA = WdBase + (size_t)ci * C_   + k0 + kk0;
        const float* srcB = WcBase + (size_t)ci * KDIM + k0 + kk0;
        #pragma unroll
        for (int u = 0; u < 8; u++) WdS[ci][kk0 + u] = srcA[u];
        #pragma unroll
        for (int u = 0; u < 8; u++) WcS[ci][kk0 + u] = srcB[u];
        __syncthreads();
        #pragma unroll
        for (int kk = 0; kk < 32; kk++) {
            float a[4], bb[4];
            #pragma unroll
            for (int i = 0; i < 4; i++) a[i]  = WdS[ty * 4 + i][kk];
            #pragma unroll
            for (int j = 0; j < 4; j++) bb[j] = WcS[tx * 4 + j][kk];
            #pragma unroll
            for (int i = 0; i < 4; i++)
                #pragma unroll
                for (int j = 0; j < 4; j++) acc[i][j] += a[i] * bb[j];
        }
        __syncthreads();
    }
    #pragma unroll
    for (int i = 0; i < 4; i++) {
        const int c = ct * 64 + ty * 4 + i;
        #pragma unroll
        for (int j = 0; j < 4; j++) {
            const int o = et * 64 + tx * 4 + j;
            Mt[(size_t)o * KDIM + d * C_ + c] = __float2half(acc[i][j]);
        }
    }
}

// ---------------------------------------------------------------------------
// Kernel 3: HMMA implicit-GEMM. BM=64, BN=128, BK=64, 3-stage cp.async.
// 8 warps (2m x 4n), each 32x32. 2048 CTAs, 2 CTAs/SM -> 16 warps/SM.
// ---------------------------------------------------------------------------
__global__ __launch_bounds__(256, 2) void conv_gemm_hmma(const float* __restrict__ bias,
                                                         float* __restrict__ out)
{
    extern __shared__ __align__(1024) char smem[];
    const uint32_t sbase = smem_u32(smem);

    const int t    = threadIdx.x;
    const int warp = t >> 5, lane = t & 31;
    const int bx   = blockIdx.x;
    const int m0   = (bx >> 1) * BM;
    const int n0   = (bx & 1) * BN;

    // ---- producer setup ----
    // A: 64 rows x 8 chunks(16B) = 512 cp -> 2 per thread
    const int arow   = t >> 2;
    const int acpair = (t & 3) * 2;           // chunks acpair, acpair+1
    // B: 128 rows x 8 chunks = 1024 cp -> 4 per thread
    const int brow = t >> 1;
    const int bc0  = (t & 1) * 4;             // chunks bc0..bc0+3

    const int m = m0 + arow;
    const int x = m & 63;
    const int y = (m >> 6) & 63;
    const int b = m >> 12;
    const __half* a_src_base = g_pad + (size_t)((b * HP + y + 1) * WP + (x + 1)) * C_;
    const __half* b_src_base = Mt + (size_t)(n0 + brow) * KDIM;

    uint32_t a_dst[2], b_dst[4];
    #pragma unroll
    for (int j = 0; j < 2; j++)
        a_dst[j] = (uint32_t)(arow * 128 + (((acpair + j) ^ (arow & 7)) << 4));
    #pragma unroll
    for (int j = 0; j < 4; j++)
        b_dst[j] = (uint32_t)(A_BYTES + brow * 128 + (((bc0 + j) ^ (brow & 7)) << 4));

    // ---- consumer setup: warp tile 32x32 ----
    const int wm = (warp >> 2) * 32;          // 2 warps in M
    const int wn = (warp & 3) * 32;           // 4 warps in N
    const int swz  = lane & 7;
    const int a_hi = lane >> 4;               // 0/1
    const int b_hi = (lane >> 3) & 1;         // 0/1

    uint32_t a_row_off[2], b_row_off[2];
    #pragma unroll
    for (int im = 0; im < 2; im++)
        a_row_off[im] = (uint32_t)((wm + im * 16 + (lane & 15)) * 128);
    #pragma unroll
    for (int j2 = 0; j2 < 2; j2++)
        b_row_off[j2] = (uint32_t)(A_BYTES +
            (wn + j2 * 16 + ((lane >> 4) << 3) + (lane & 7)) * 128);

    float acc[2][4][4];
    #pragma unroll
    for (int i = 0; i < 2; i++)
        #pragma unroll
        for (int j = 0; j < 4; j++)
            #pragma unroll
            for (int r = 0; r < 4; r++) acc[i][j][r] = 0.0f;

    #define LOAD_STAGE(KT, S)                                                     \
    do {                                                                          \
        const int d_   = (KT) >> 2;                                               \
        const int coff = ((KT) & 3) * 64 + acpair * 8;                            \
        const __half* asrc = a_src_base + c_shift[d_] * C_ + coff;                \
        const __half* bsrc = b_src_base + (KT) * 64 + bc0 * 8;                    \
        const uint32_t sb  = sbase + (S) * STAGE_BYTES;                           \
        _Pragma("unroll")                                                         \
        for (int j = 0; j < 2; j++) cp_async16(sb + a_dst[j], asrc + j * 8);      \
        _Pragma("unroll")                                                         \
        for (int j = 0; j < 4; j++) cp_async16(sb + b_dst[j], bsrc + j * 8);      \
        cp_commit();                                                              \
    } while (0)

    LOAD_STAGE(0, 0);
    LOAD_STAGE(1, 1);

    for (int s = 0; s < NKT; s++) {
        if (s + 2 < NKT) cp_wait<1>(); else cp_wait<0>();
        __syncthreads();
        if (s + 2 < NKT) LOAD_STAGE(s + 2, (s + 2) % NSTAGE);

        const uint32_t sb = sbase + (s % NSTAGE) * STAGE_BYTES;
        #pragma unroll
        for (int kk = 0; kk < 4; kk++) {
            uint32_t afr[2][4];
            uint32_t bfr[4][2];
            #pragma unroll
            for (int im = 0; im < 2; im++)
                ldsm4(afr[im][0], afr[im][1], afr[im][2], afr[im][3],
                      sb + a_row_off[im] + (((kk * 2 + a_hi) ^ swz) << 4));
            #pragma unroll
            for (int j2 = 0; j2 < 2; j2++) {
                uint32_t r0, r1, r2, r3;
                ldsm4(r0, r1, r2, r3,
                      sb + b_row_off[j2] + (((kk * 2 + b_hi) ^ swz) << 4));
                bfr[j2 * 2 + 0][0] = r0; bfr[j2 * 2 + 0][1] = r1;
                bfr[j2 * 2 + 1][0] = r2; bfr[j2 * 2 + 1][1] = r3;
            }
            #pragma unroll
            for (int im = 0; im < 2; im++)
                #pragma unroll
                for (int jn = 0; jn < 4; jn++)
                    mma16816(acc[im][jn], afr[im], bfr[jn]);
        }
    }

    // ---- epilogue ----
    #pragma unroll
    for (int jn = 0; jn < 4; jn++) {
        const int n = n0 + wn + jn * 8 + (lane & 3) * 2;
        const float2 bv = *(const float2*)&bias[n];
        #pragma unroll
        for (int im = 0; im < 2; im++) {
            const int mrow = m0 + wm + im * 16 + (lane >> 2);
            float2 v0, v1;
            v0.x = acc[im][jn][0] + bv.x;  v0.y = acc[im][jn][1] + bv.y;
            v1.x = acc[im][jn][2] + bv.x;  v1.y = acc[im][jn][3] + bv.y;
            *(float2*)&out[(size_t)mrow * NDIM + n]       = v0;
            *(float2*)&out[(size_t)(mrow + 8) * NDIM + n] = v1;
        }
    }
}

// ---------------------------------------------------------------------------
extern "C" void kernel_launch(void* const* d_in, const int* in_sizes, int n_in,
                              void* d_out, int out_size)
{
    const float* grid = (const float*)d_in[0];
    const float* Wd   = (const float*)d_in[1];
    const float* Wc   = (const float*)d_in[2];
    const float* bc   = (const float*)d_in[3];
    float* out        = (float*)d_out;

    cudaFuncSetAttribute(conv_gemm_hmma, cudaFuncAttributeMaxDynamicSharedMemorySize, SM_TOTAL);

    pad_convert_kernel<<<(B_ * HP * WP * 32) / 256, 256>>>(grid);
    fold_weights_kernel<<<128, 256>>>(Wd, Wc);
    conv_gemm_hmma<<<(NPOS / BM) * (NDIM / BN), 256, SM_TOTAL>>>(bc, out);
}